// round 3
// baseline (speedup 1.0000x reference)
#include <cuda_runtime.h>
#include <cstdint>

#define NB 2
#define SQ 2048
#define DM 1024
#define NH 16
#define DK 64

constexpr size_t QKV_ELEMS = (size_t)NB * NH * SQ * DK;   // 4,194,304
constexpr size_t CTX_ELEMS = (size_t)NB * SQ * DM;        // 4,194,304
constexpr size_t OUT_ELEMS = (size_t)NB * SQ * DM;        // 4,194,304

__device__ float g_q[QKV_ELEMS];
__device__ float g_k[QKV_ELEMS];
__device__ float g_v[QKV_ELEMS];
__device__ float g_ctx[CTX_ELEMS];
__device__ float g_invl[(size_t)NB * NH * SQ];  // 65536 per-row 1/denominator

__device__ __forceinline__ uint32_t f2tf(float x) {
    uint32_t r;
    asm("cvt.rna.tf32.f32 %0, %1;" : "=r"(r) : "f"(x));
    return r;
}
__device__ __forceinline__ float f2tff(float x) { return __uint_as_float(f2tf(x)); }

__device__ __forceinline__ void mma8(float* c, const uint32_t* a, const uint32_t* b) {
    asm volatile(
        "mma.sync.aligned.m16n8k8.row.col.f32.tf32.tf32.f32 "
        "{%0,%1,%2,%3},{%4,%5,%6,%7},{%8,%9},{%0,%1,%2,%3};"
        : "+f"(c[0]), "+f"(c[1]), "+f"(c[2]), "+f"(c[3])
        : "r"(a[0]), "r"(a[1]), "r"(a[2]), "r"(a[3]), "r"(b[0]), "r"(b[1]));
}

// Column permutation within each 8-wide k-group: value for column c stored at
// position ((c&3)<<1)|(c>>2).  Then the MMA fragment pair (col tg, col tg+4)
// sits at positions (2tg, 2tg+1): ONE aligned float2 LDS instead of two LDS.

// ============================================================================
// GEMM: C = A @ W^T + bias.  A [4096,1024] rm, W [1024,1024] rm.
// MODE 1: z selects among QKV projections; output head-split into g_q/g_k/g_v.
// MODE 0: A = g_ctx, output row-major to outp.
// Block 128x128, BK=32, 256 threads (8 warps = 4m x 2n, warp tile 32x64).
// ============================================================================
template <int MODE>
__global__ __launch_bounds__(256) void gemm_kernel(
    const float* __restrict__ A0, const float* __restrict__ A1, const float* __restrict__ A2,
    const float* __restrict__ W0, const float* __restrict__ W1, const float* __restrict__ W2,
    const float* __restrict__ b0, const float* __restrict__ b1, const float* __restrict__ b2,
    float* __restrict__ outp)
{
    __shared__ float As[128][36];
    __shared__ float Ws[128][36];

    const int tid = threadIdx.x;
    const int warp = tid >> 5, lane = tid & 31;
    const int g = lane >> 2, tg = lane & 3;
    const int warp_m = warp & 3, warp_n = warp >> 2;
    const int z = (MODE == 1) ? blockIdx.z : 0;

    const float* Aptr;
    const float* Wm;
    const float* bias;
    if (MODE == 1) {
        Aptr = (z == 0) ? A0 : (z == 1) ? A1 : A2;
        Wm   = (z == 0) ? W0 : (z == 1) ? W1 : W2;
        bias = (z == 0) ? b0 : (z == 1) ? b1 : b2;
    } else {
        Aptr = g_ctx; Wm = W0; bias = b0;
    }

    const int rowA0 = blockIdx.y * 128;
    const int col0  = blockIdx.x * 128;

    float acc[2][8][4];
#pragma unroll
    for (int mt = 0; mt < 2; mt++)
#pragma unroll
        for (int nt = 0; nt < 8; nt++)
#pragma unroll
            for (int c = 0; c < 4; c++) acc[mt][nt][c] = 0.f;

    for (int k0 = 0; k0 < DM; k0 += 32) {
        __syncthreads();
#pragma unroll
        for (int i = 0; i < 4; i++) {
            int lin = tid + i * 256;
            int r = lin >> 3, c4 = lin & 7;
            int base = (c4 >> 1) * 8 + (c4 & 1);  // permuted position of col 4*c4
            float4 va = *(const float4*)(Aptr + (size_t)(rowA0 + r) * DM + k0 + c4 * 4);
            As[r][base + 0] = f2tff(va.x);
            As[r][base + 2] = f2tff(va.y);
            As[r][base + 4] = f2tff(va.z);
            As[r][base + 6] = f2tff(va.w);
            float4 vw = *(const float4*)(Wm + (size_t)(col0 + r) * DM + k0 + c4 * 4);
            Ws[r][base + 0] = f2tff(vw.x);
            Ws[r][base + 2] = f2tff(vw.y);
            Ws[r][base + 4] = f2tff(vw.z);
            Ws[r][base + 6] = f2tff(vw.w);
        }
        __syncthreads();
#pragma unroll
        for (int ks8 = 0; ks8 < 4; ks8++) {
            const int kk = ks8 * 8;
            uint32_t af[2][4];
#pragma unroll
            for (int mt = 0; mt < 2; mt++) {
                int r = warp_m * 32 + mt * 16 + g;
                float2 lo = *(const float2*)&As[r][kk + 2 * tg];
                float2 hi = *(const float2*)&As[r + 8][kk + 2 * tg];
                af[mt][0] = __float_as_uint(lo.x);
                af[mt][1] = __float_as_uint(hi.x);
                af[mt][2] = __float_as_uint(lo.y);
                af[mt][3] = __float_as_uint(hi.y);
            }
#pragma unroll
            for (int nt = 0; nt < 8; nt++) {
                int n = warp_n * 64 + nt * 8 + g;
                float2 bw = *(const float2*)&Ws[n][kk + 2 * tg];
                uint32_t bf[2] = {__float_as_uint(bw.x), __float_as_uint(bw.y)};
#pragma unroll
                for (int mt = 0; mt < 2; mt++) mma8(acc[mt][nt], af[mt], bf);
            }
        }
    }

#pragma unroll
    for (int mt = 0; mt < 2; mt++) {
        int row = rowA0 + warp_m * 32 + mt * 16 + g;
#pragma unroll
        for (int nt = 0; nt < 8; nt++) {
            int col = col0 + warp_n * 64 + nt * 8 + tg * 2;
            float bv0 = bias[col], bv1 = bias[col + 1];
            float c0 = acc[mt][nt][0] + bv0, c1 = acc[mt][nt][1] + bv1;
            float c2 = acc[mt][nt][2] + bv0, c3 = acc[mt][nt][3] + bv1;
            if (MODE == 0) {
                *(float2*)(outp + (size_t)row * DM + col) = make_float2(c0, c1);
                *(float2*)(outp + (size_t)(row + 8) * DM + col) = make_float2(c2, c3);
            } else {
                float* dst = (z == 0) ? g_q : (z == 1) ? g_k : g_v;
                int b_ = row >> 11, s_ = row & 2047;
                int h_ = col >> 6, d_ = col & 63;
                size_t base = (((size_t)b_ * NH + h_) * SQ + s_) * DK + d_;
                *(float2*)(dst + base) = make_float2(c0, c1);
                *(float2*)(dst + base + 8 * DK) = make_float2(c2, c3);
            }
        }
    }
}

// ============================================================================
// SINGLE-PASS fused attention.  One block = one (b,h) x 64-row q-tile,
// 128 threads (4 warps, 16 q-rows each).  For each 128-key tile:
//   S = q @ k^T / 8  (tf32 MMA), e = exp(S)  (no max subtraction: |S| < ~7),
//   write UNNORMALIZED e to attn gmem, l += rowsum(e), ctx += e @ V (MMA).
// Epilogue: ctx *= 1/l, store 1/l per row; norm_kernel scales attn afterwards.
// Smem: qs 64x68 + kv 128x68 (K then V) + ps 64x132 = 86016 B -> 2 blocks/SM.
// qs/K use permuted columns (float2 frag loads); V stored plain.
// ============================================================================
__global__ __launch_bounds__(128) void attn_kernel(float* __restrict__ attn_out)
{
    extern __shared__ float sm[];
    float(*qs)[68]  = (float(*)[68])sm;
    float(*kv)[68]  = (float(*)[68])(sm + 64 * 68);
    float(*ps)[132] = (float(*)[132])(sm + 64 * 68 + 128 * 68);

    const int tid = threadIdx.x;
    const int warp = tid >> 5, lane = tid & 31;
    const int g = lane >> 2, tg = lane & 3;
    const int qt = blockIdx.x, bh = blockIdx.y;
    const int wrow = warp * 16;
    // permuted position of column 2*tg within an 8-group (pair partner at +2)
    const int p0 = ((tg & 1) << 2) | (tg >> 1);

    const float* qb = g_q + ((size_t)bh * SQ + qt * 64) * DK;
    const float* kb = g_k + (size_t)bh * SQ * DK;
    const float* vb = g_v + (size_t)bh * SQ * DK;

    // load q tile, tf32-rounded, permuted columns
#pragma unroll
    for (int i = 0; i < 8; i++) {
        int lin = tid + i * 128;
        int r = lin >> 4, c4 = lin & 15;
        int base = (c4 >> 1) * 8 + (c4 & 1);
        float4 v = *(const float4*)(qb + (size_t)r * DK + c4 * 4);
        qs[r][base + 0] = f2tff(v.x);
        qs[r][base + 2] = f2tff(v.y);
        qs[r][base + 4] = f2tff(v.z);
        qs[r][base + 6] = f2tff(v.w);
    }

    float ctx[8][4];
#pragma unroll
    for (int nt = 0; nt < 8; nt++)
#pragma unroll
        for (int c = 0; c < 4; c++) ctx[nt][c] = 0.f;
    float l0 = 0.f, l1 = 0.f;
    float sacc[16][4];

    for (int kt = 0; kt < 16; kt++) {
        // ---- load K tile (permuted) ----
#pragma unroll
        for (int i = 0; i < 16; i++) {
            int lin = tid + i * 128;
            int r = lin >> 4, c4 = lin & 15;
            int base = (c4 >> 1) * 8 + (c4 & 1);
            float4 v = *(const float4*)(kb + ((size_t)kt * 128 + r) * DK + c4 * 4);
            kv[r][base + 0] = f2tff(v.x);
            kv[r][base + 2] = f2tff(v.y);
            kv[r][base + 4] = f2tff(v.z);
            kv[r][base + 6] = f2tff(v.w);
        }
        __syncthreads();

        // ---- S = q @ k^T ----
#pragma unroll
        for (int nt = 0; nt < 16; nt++)
#pragma unroll
            for (int c = 0; c < 4; c++) sacc[nt][c] = 0.f;
#pragma unroll
        for (int d8 = 0; d8 < 8; d8++) {
            const int kk = d8 * 8;
            float2 lo = *(const float2*)&qs[wrow + g][kk + 2 * tg];
            float2 hi = *(const float2*)&qs[wrow + 8 + g][kk + 2 * tg];
            uint32_t a[4] = {__float_as_uint(lo.x), __float_as_uint(hi.x),
                             __float_as_uint(lo.y), __float_as_uint(hi.y)};
#pragma unroll
            for (int nt = 0; nt < 16; nt++) {
                float2 bw = *(const float2*)&kv[nt * 8 + g][kk + 2 * tg];
                uint32_t b[2] = {__float_as_uint(bw.x), __float_as_uint(bw.y)};
                mma8(sacc[nt], a, b);
            }
        }

        // ---- e = exp(S/8); write unnormalized attn; stage P; rowsum ----
        const size_t arow0 = ((size_t)bh * SQ + qt * 64 + wrow + g) * SQ + kt * 128;
        const size_t arow1 = arow0 + (size_t)8 * SQ;
#pragma unroll
        for (int nt = 0; nt < 16; nt++) {
            float e00 = __expf(sacc[nt][0] * 0.125f);
            float e01 = __expf(sacc[nt][1] * 0.125f);
            float e10 = __expf(sacc[nt][2] * 0.125f);
            float e11 = __expf(sacc[nt][3] * 0.125f);
            l0 += e00 + e01;
            l1 += e10 + e11;
            int cc = nt * 8 + tg * 2;
            *(float2*)(attn_out + arow0 + cc) = make_float2(e00, e01);
            *(float2*)(attn_out + arow1 + cc) = make_float2(e10, e11);
            ps[wrow + g][nt * 8 + p0]         = f2tff(e00);
            ps[wrow + g][nt * 8 + p0 + 2]     = f2tff(e01);
            ps[wrow + 8 + g][nt * 8 + p0]     = f2tff(e10);
            ps[wrow + 8 + g][nt * 8 + p0 + 2] = f2tff(e11);
        }
        __syncthreads();  // all warps done reading K before V overwrites

        // ---- load V tile (plain layout) ----
#pragma unroll
        for (int i = 0; i < 16; i++) {
            int lin = tid + i * 128;
            int r = lin >> 4, c4 = lin & 15;
            float4 v = *(const float4*)(vb + ((size_t)kt * 128 + r) * DK + c4 * 4);
            kv[r][c4 * 4 + 0] = f2tff(v.x);
            kv[r][c4 * 4 + 1] = f2tff(v.y);
            kv[r][c4 * 4 + 2] = f2tff(v.z);
            kv[r][c4 * 4 + 3] = f2tff(v.w);
        }
        __syncthreads();

        // ---- ctx += P @ V ----
#pragma unroll
        for (int k8 = 0; k8 < 16; k8++) {
            const int kk = k8 * 8;
            float2 lo = *(const float2*)&ps[wrow + g][kk + 2 * tg];
            float2 hi = *(const float2*)&ps[wrow + 8 + g][kk + 2 * tg];
            uint32_t a[4] = {__float_as_uint(lo.x), __float_as_uint(hi.x),
                             __float_as_uint(lo.y), __float_as_uint(hi.y)};
#pragma unroll
            for (int nt2 = 0; nt2 < 8; nt2++) {
                uint32_t b[2] = {__float_as_uint(kv[kk + tg][nt2 * 8 + g]),
                                 __float_as_uint(kv[kk + tg + 4][nt2 * 8 + g])};
                mma8(ctx[nt2], a, b);
            }
        }
        __syncthreads();  // PV done before next K load overwrites kv
    }

    // ---- epilogue: reduce row sums, scale ctx, store inv ----
    l0 += __shfl_xor_sync(0xffffffffu, l0, 1);
    l0 += __shfl_xor_sync(0xffffffffu, l0, 2);
    l1 += __shfl_xor_sync(0xffffffffu, l1, 1);
    l1 += __shfl_xor_sync(0xffffffffu, l1, 2);
    const float inv0 = 1.f / l0, inv1 = 1.f / l1;

    if (tg == 0) {
        size_t rbase = (size_t)bh * SQ + qt * 64 + wrow + g;
        g_invl[rbase] = inv0;
        g_invl[rbase + 8] = inv1;
    }

    const int b_ = bh >> 4, h_ = bh & 15;
    const int r0 = qt * 64 + wrow + g;
    const size_t crow = ((size_t)b_ * SQ + r0) * DM + h_ * 64;
#pragma unroll
    for (int nt2 = 0; nt2 < 8; nt2++) {
        int cc = nt2 * 8 + tg * 2;
        *(float2*)(g_ctx + crow + cc) =
            make_float2(ctx[nt2][0] * inv0, ctx[nt2][1] * inv0);
        *(float2*)(g_ctx + crow + (size_t)8 * DM + cc) =
            make_float2(ctx[nt2][2] * inv1, ctx[nt2][3] * inv1);
    }
}

// ============================================================================
// Normalize attn in place: attn[row][*] *= g_invl[row].  float4 elementwise.
// ============================================================================
__global__ __launch_bounds__(256) void norm_kernel(float* __restrict__ attn)
{
    size_t i = (size_t)blockIdx.x * 256 + threadIdx.x;  // float4 index
    float inv = g_invl[i >> 9];                         // 512 float4 per row
    float4* p = (float4*)attn;
    float4 v = p[i];
    v.x *= inv; v.y *= inv; v.z *= inv; v.w *= inv;
    p[i] = v;
}

extern "C" void kernel_launch(void* const* d_in, const int* in_sizes, int n_in,
                              void* d_out, int out_size)
{
    const float* Q   = (const float*)d_in[0];
    const float* K   = (const float*)d_in[1];
    const float* V   = (const float*)d_in[2];
    const float* Wq  = (const float*)d_in[3];
    const float* bq  = (const float*)d_in[4];
    const float* Wk  = (const float*)d_in[5];
    const float* bk  = (const float*)d_in[6];
    const float* Wv  = (const float*)d_in[7];
    const float* bv  = (const float*)d_in[8];
    const float* Wfc = (const float*)d_in[9];
    const float* bfc = (const float*)d_in[10];

    float* out  = (float*)d_out;
    float* attn = out + OUT_ELEMS;

    cudaFuncSetAttribute(attn_kernel, cudaFuncAttributeMaxDynamicSharedMemorySize, 86016);

    // QKV projections (z selects q/k/v), head-split outputs into g_q/g_k/g_v
    gemm_kernel<1><<<dim3(8, 32, 3), 256>>>(Q, K, V, Wq, Wk, Wv, bq, bk, bv, nullptr);
    // Single-pass attention: writes unnormalized exp(S) to attn, ctx to g_ctx
    attn_kernel<<<dim3(32, 32), 128, 86016>>>(attn);
    // Output projection (independent of attn normalization)
    gemm_kernel<0><<<dim3(8, 32, 1), 256>>>(nullptr, nullptr, nullptr,
                                            Wfc, nullptr, nullptr,
                                            bfc, nullptr, nullptr, out);
    // Normalize attn rows
    norm_kernel<<<131072, 256>>>(attn);
}